// round 1
// baseline (speedup 1.0000x reference)
#include <cuda_runtime.h>

#define EPSF 1e-7f
#define P_TOT 900
#define NCH 144
#define COUT 32

// Scratch (no allocations allowed): rr and zz ping through device globals.
static __device__ float g_zz[P_TOT * NCH * COUT];
static __device__ float g_rr[P_TOT * NCH * COUT];

__device__ __forceinline__ float wredsum(float v) {
#pragma unroll
    for (int o = 16; o; o >>= 1) v += __shfl_xor_sync(0xffffffffu, v, o);
    return v;
}

extern __shared__ float smem[];

// One CTA per parent position p (900 CTAs, 256 threads = 8 warps).
// Warp w handles output capsules c = {w, w+8, w+16, w+24}.
// mode 0: first iteration (rr uniform 1/32), compute M+E, write zz
// mode 1: read rr, compute M+E, write zz
// mode 2: read rr, compute M only, write final outputs
__global__ void __launch_bounds__(256) me_kernel(
    const float* __restrict__ pose, const float* __restrict__ W,
    const float* __restrict__ beta_a, const float* __restrict__ beta_v,
    float* __restrict__ out, int mode, float lambd)
{
    float* sA  = smem;            // child poses [144][16] pad17 -> 2448 floats
    float* sRR = sA + 2448;       // rr [144][32] pad33       -> 4752 floats
    float* sZZ = sRR + 4752;      // zz [144][32] pad33       -> 4752 floats
    float* sV  = sZZ + 4752;      // per-warp votes [8][144][16] pad17 -> 19584

    const int p = blockIdx.x;
    const int t = threadIdx.x;
    const int lane = t & 31, w = t >> 5;
    const int pr = p / 30, pcl = p % 30;

    // Gather the 9 child positions x 16 capsule poses (coalesced-ish 64B rows).
    for (int idx = t; idx < NCH * 16; idx += 256) {
        int n = idx >> 4, e = idx & 15;
        int k = n >> 4, ci = n & 15;               // n = k*16 + ci, k = kr*3+kc
        int q = (pr + k / 3) * 32 + pcl + (k % 3); // child flat position
        sA[n * 17 + e] = pose[q * 256 + ci * 16 + e];
    }
    if (mode > 0) {
        const float* rrp = g_rr + p * (NCH * COUT);
        for (int idx = t; idx < NCH * COUT; idx += 256)
            sRR[(idx >> 5) * 33 + (idx & 31)] = rrp[idx];
    }
    __syncthreads();

    float* myV = sV + w * 2448;

#pragma unroll 1
    for (int cc = 0; cc < 4; cc++) {
        const int c = cc * 8 + w;

        // ---- pass 1: compute votes (kept in SMEM), accumulate rs, sum rr*v
        float rs = 0.f;
        float srv[16];
#pragma unroll
        for (int e = 0; e < 16; e++) srv[e] = 0.f;
        float rrk[5];

#pragma unroll 1
        for (int k = 0; k < 5; k++) {
            int n = lane + (k << 5);
            rrk[k] = 0.f;
            if (n < NCH) {
                float rrn = (mode == 0) ? 0.03125f : sRR[n * 33 + c];
                rrk[k] = rrn;
                const float4* Bp =
                    reinterpret_cast<const float4*>(W + ((size_t)(n * COUT + c)) * 16);
                float4 b0 = Bp[0], b1 = Bp[1], b2 = Bp[2], b3 = Bp[3];
                float a[16];
#pragma unroll
                for (int e = 0; e < 16; e++) a[e] = sA[n * 17 + e];
                float v[16];
#pragma unroll
                for (int i = 0; i < 4; i++) {
                    v[i*4+0] = a[i*4+0]*b0.x + a[i*4+1]*b1.x + a[i*4+2]*b2.x + a[i*4+3]*b3.x;
                    v[i*4+1] = a[i*4+0]*b0.y + a[i*4+1]*b1.y + a[i*4+2]*b2.y + a[i*4+3]*b3.y;
                    v[i*4+2] = a[i*4+0]*b0.z + a[i*4+1]*b1.z + a[i*4+2]*b2.z + a[i*4+3]*b3.z;
                    v[i*4+3] = a[i*4+0]*b0.w + a[i*4+1]*b1.w + a[i*4+2]*b2.w + a[i*4+3]*b3.w;
                }
                rs += rrn;
#pragma unroll
                for (int e = 0; e < 16; e++) {
                    myV[n * 17 + e] = v[e];
                    srv[e] += rrn * v[e];
                }
            }
        }
        rs = wredsum(rs);
#pragma unroll
        for (int e = 0; e < 16; e++) srv[e] = wredsum(srv[e]);
        const float inv_rs = 1.f / rs;
        float mean[16];
#pragma unroll
        for (int e = 0; e < 16; e++) mean[e] = srv[e] * inv_rs;

        // ---- pass 2: exact variance sum rr*(v-m)^2 from SMEM votes
        float sdv[16];
#pragma unroll
        for (int e = 0; e < 16; e++) sdv[e] = 0.f;
#pragma unroll 1
        for (int k = 0; k < 5; k++) {
            int n = lane + (k << 5);
            if (n < NCH) {
                float rrn = rrk[k];
#pragma unroll
                for (int e = 0; e < 16; e++) {
                    float d = myV[n * 17 + e] - mean[e];
                    sdv[e] += rrn * d * d;
                }
            }
        }
#pragma unroll
        for (int e = 0; e < 16; e++) sdv[e] = wredsum(sdv[e]);

        float logstd_sum = 0.f;
        float i2v[16];
#pragma unroll
        for (int e = 0; e < 16; e++) {
            float var = sdv[e] * inv_rs;
            float sd = sqrtf(var);
            logstd_sum += logf(sd + EPSF);
            i2v[e] = 0.5f / var;
        }
        float cost_sum = 16.f * beta_v[c] + rs * logstd_sum;
        float act = 1.f / (1.f + expf(-lambd * (beta_a[c] - cost_sum)));

        if (mode == 2) {
            if (lane == 0) {
                out[p * COUT + c] = act;
                float* op = out + 28800 + (size_t)p * 512 + c * 16;
#pragma unroll
                for (int e = 0; e < 16; e++) op[e] = mean[e];
            }
        } else {
            // ---- E step: zz = log(act+eps) + prob_main + prob_exp
            float zb = logf(act + EPSF) - logstd_sum;
#pragma unroll 1
            for (int k = 0; k < 5; k++) {
                int n = lane + (k << 5);
                if (n < NCH) {
                    float pe = 0.f;
#pragma unroll
                    for (int e = 0; e < 16; e++) {
                        float d = myV[n * 17 + e] - mean[e];
                        pe += d * d * i2v[e];
                    }
                    sZZ[n * 33 + c] = zb - pe;
                }
            }
        }
    }

    if (mode != 2) {
        __syncthreads();
        float* zzp = g_zz + (size_t)p * (NCH * COUT);
        for (int idx = t; idx < NCH * COUT; idx += 256)
            zzp[idx] = sZZ[(idx >> 5) * 33 + (idx & 31)];
    }
}

// Softmax over the parent axis p (900) for every (n, c).
// One block per n (144 blocks), 256 threads: c = lane, warp = p-stripe.
__global__ void __launch_bounds__(256) softmax_kernel()
{
    const int n = blockIdx.x;
    const int t = threadIdx.x;
    const int c = t & 31, w = t >> 5;
    __shared__ float sM[256], sS[256];

    float m = -1e30f, s = 0.f;
    for (int p = w; p < P_TOT; p += 8) {
        float z = g_zz[(size_t)p * (NCH * COUT) + n * COUT + c];
        float nm = fmaxf(m, z);
        s = s * expf(m - nm) + expf(z - nm);
        m = nm;
    }
    sM[t] = m;
    sS[t] = s;
    __syncthreads();
    if (t < 32) {
        float M = sM[t];
#pragma unroll
        for (int i = 1; i < 8; i++) M = fmaxf(M, sM[i * 32 + t]);
        float S = 0.f;
#pragma unroll
        for (int i = 0; i < 8; i++) S += sS[i * 32 + t] * expf(sM[i * 32 + t] - M);
        sM[t] = M;
        sS[t] = 1.f / S;
    }
    __syncthreads();
    const float M = sM[c], Sinv = sS[c];
    for (int p = w; p < P_TOT; p += 8) {
        size_t idx = (size_t)p * (NCH * COUT) + n * COUT + c;
        g_rr[idx] = expf(g_zz[idx] - M) * Sinv;
    }
}

extern "C" void kernel_launch(void* const* d_in, const int* in_sizes, int n_in,
                              void* d_out, int out_size)
{
    // inputs: [0] input_act (unused by reference math), [1] input_pose,
    //         [2] transformation_weights, [3] beta_a, [4] beta_v
    const float* pose = (const float*)d_in[1];
    const float* W    = (const float*)d_in[2];
    const float* ba   = (const float*)d_in[3];
    const float* bv   = (const float*)d_in[4];
    float* out = (float*)d_out;

    const size_t shmem = (2448 + 4752 + 4752 + 8 * 2448) * sizeof(float); // 126144 B
    cudaFuncSetAttribute(me_kernel, cudaFuncAttributeMaxDynamicSharedMemorySize,
                         (int)shmem);

    // routing iter 0: lambd = 0
    me_kernel<<<P_TOT, 256, shmem>>>(pose, W, ba, bv, out, 0, 0.0f);
    softmax_kernel<<<NCH, 256>>>();
    // routing iter 1: lambd = 0.01*(1-0.95) = 5e-4
    me_kernel<<<P_TOT, 256, shmem>>>(pose, W, ba, bv, out, 1, 0.0005f);
    softmax_kernel<<<NCH, 256>>>();
    // routing iter 2 (final, M-step only): lambd = 0.01*(1-0.9025) = 9.75e-4
    me_kernel<<<P_TOT, 256, shmem>>>(pose, W, ba, bv, out, 2, 0.000975f);
}

// round 2
// speedup vs baseline: 2.3299x; 2.3299x over previous
#include <cuda_runtime.h>

#define EPSF 1e-7f
#define P_TOT 900
#define NCH 144
#define COUT 32

// Scratch (no allocations allowed)
static __device__ float g_zz[P_TOT * NCH * COUT];
static __device__ float g_rr[P_TOT * NCH * COUT];
static __device__ float g_Wt[NCH * COUT * 16];   // [c][k][n][j]

__device__ __forceinline__ float wredsum(float v) {
#pragma unroll
    for (int o = 16; o; o >>= 1) v += __shfl_xor_sync(0xffffffffu, v, o);
    return v;
}
__device__ __forceinline__ float4 wred4(float4 v) {
    v.x = wredsum(v.x); v.y = wredsum(v.y);
    v.z = wredsum(v.z); v.w = wredsum(v.w);
    return v;
}

// Transpose W[(n*32+c)*16 + k*4 + j] -> Wt[((c*4+k)*144 + n)*4 + j]
__global__ void __launch_bounds__(256) wtrans_kernel(const float* __restrict__ W) {
    int i = blockIdx.x * 256 + threadIdx.x;       // over 144*32*4 float4 groups
    if (i < NCH * COUT * 4) {
        int k = i & 3, c = (i >> 2) & 31, n = i >> 7;
        float4 v = reinterpret_cast<const float4*>(W)[i];
        reinterpret_cast<float4*>(g_Wt)[(c * 4 + k) * NCH + n] = v;
    }
}

extern __shared__ float smem[];

// One CTA per parent p. 8 warps; warp w owns c = {w, w+8, w+16, w+24}.
// mode 0: rr uniform, M+E, write zz.  mode 1: read rr, M+E, write zz.
// mode 2: read rr, M only, write outputs.
__global__ void __launch_bounds__(256, 2) me_kernel(
    const float* __restrict__ pose,
    const float* __restrict__ beta_a, const float* __restrict__ beta_v,
    float* __restrict__ out, int mode, float lambd)
{
    float* sA  = smem;                    // [144][20]   (rows 80B, 16B aligned)
    float* sRZ = smem + 2880;             // [144][33]   rr in, zz out (aliased)
    float* sV  = smem + 2880 + 4752;      // 8 x [144][16] votes (xor-swizzled)

    const int p = blockIdx.x;
    const int t = threadIdx.x;
    const int lane = t & 31, w = t >> 5;
    const int pr = p / 30, pcl = p % 30;

    // Gather child poses, vectorized (float4)
    for (int idx = t; idx < NCH * 4; idx += 256) {
        int n = idx >> 2, v = idx & 3;
        int k = n >> 4, ci = n & 15;
        int q = (pr + k / 3) * 32 + pcl + (k % 3);
        float4 val = reinterpret_cast<const float4*>(pose + q * 256 + ci * 16)[v];
        *reinterpret_cast<float4*>(sA + n * 20 + v * 4) = val;
    }
    if (mode > 0) {
        const float* rrp = g_rr + (size_t)p * (NCH * COUT);
        for (int idx = t; idx < NCH * COUT; idx += 256)
            sRZ[(idx >> 5) * 33 + (idx & 31)] = rrp[idx];
    }
    __syncthreads();

    float* myV = sV + w * (NCH * 16);

#pragma unroll 1
    for (int cc = 0; cc < 4; cc++) {
        const int c = cc * 8 + w;
        float rs = 0.f;
        float4 s0 = {0,0,0,0}, s1 = {0,0,0,0}, s2 = {0,0,0,0}, s3 = {0,0,0,0};
        float4 q0 = {0,0,0,0}, q1 = {0,0,0,0}, q2 = {0,0,0,0}, q3 = {0,0,0,0};

#pragma unroll 1
        for (int k = 0; k < 5; k++) {
            int n = lane + (k << 5);
            if (n < NCH) {
                float rrn = (mode == 0) ? 0.03125f : sRZ[n * 33 + c];
                const float4* Ap = reinterpret_cast<const float4*>(sA + n * 20);
                float4 a0 = Ap[0], a1 = Ap[1], a2 = Ap[2], a3 = Ap[3];
                const float4* Wp = reinterpret_cast<const float4*>(g_Wt) + c * 576 + n;
                float4 b0 = Wp[0], b1 = Wp[144], b2 = Wp[288], b3 = Wp[432];

                float4 v0, v1, v2, v3;
                v0.x=a0.x*b0.x+a0.y*b1.x+a0.z*b2.x+a0.w*b3.x;
                v0.y=a0.x*b0.y+a0.y*b1.y+a0.z*b2.y+a0.w*b3.y;
                v0.z=a0.x*b0.z+a0.y*b1.z+a0.z*b2.z+a0.w*b3.z;
                v0.w=a0.x*b0.w+a0.y*b1.w+a0.z*b2.w+a0.w*b3.w;
                v1.x=a1.x*b0.x+a1.y*b1.x+a1.z*b2.x+a1.w*b3.x;
                v1.y=a1.x*b0.y+a1.y*b1.y+a1.z*b2.y+a1.w*b3.y;
                v1.z=a1.x*b0.z+a1.y*b1.z+a1.z*b2.z+a1.w*b3.z;
                v1.w=a1.x*b0.w+a1.y*b1.w+a1.z*b2.w+a1.w*b3.w;
                v2.x=a2.x*b0.x+a2.y*b1.x+a2.z*b2.x+a2.w*b3.x;
                v2.y=a2.x*b0.y+a2.y*b1.y+a2.z*b2.y+a2.w*b3.y;
                v2.z=a2.x*b0.z+a2.y*b1.z+a2.z*b2.z+a2.w*b3.z;
                v2.w=a2.x*b0.w+a2.y*b1.w+a2.z*b2.w+a2.w*b3.w;
                v3.x=a3.x*b0.x+a3.y*b1.x+a3.z*b2.x+a3.w*b3.x;
                v3.y=a3.x*b0.y+a3.y*b1.y+a3.z*b2.y+a3.w*b3.y;
                v3.z=a3.x*b0.z+a3.y*b1.z+a3.z*b2.z+a3.w*b3.z;
                v3.w=a3.x*b0.w+a3.y*b1.w+a3.z*b2.w+a3.w*b3.w;

                if (mode != 2) {
                    int sw = (n >> 1) & 3;
                    float4* vp = reinterpret_cast<float4*>(myV + n * 16);
                    vp[0 ^ sw] = v0; vp[1 ^ sw] = v1; vp[2 ^ sw] = v2; vp[3 ^ sw] = v3;
                }
                rs += rrn;
                s0.x+=rrn*v0.x; s0.y+=rrn*v0.y; s0.z+=rrn*v0.z; s0.w+=rrn*v0.w;
                s1.x+=rrn*v1.x; s1.y+=rrn*v1.y; s1.z+=rrn*v1.z; s1.w+=rrn*v1.w;
                s2.x+=rrn*v2.x; s2.y+=rrn*v2.y; s2.z+=rrn*v2.z; s2.w+=rrn*v2.w;
                s3.x+=rrn*v3.x; s3.y+=rrn*v3.y; s3.z+=rrn*v3.z; s3.w+=rrn*v3.w;
                q0.x+=rrn*v0.x*v0.x; q0.y+=rrn*v0.y*v0.y; q0.z+=rrn*v0.z*v0.z; q0.w+=rrn*v0.w*v0.w;
                q1.x+=rrn*v1.x*v1.x; q1.y+=rrn*v1.y*v1.y; q1.z+=rrn*v1.z*v1.z; q1.w+=rrn*v1.w*v1.w;
                q2.x+=rrn*v2.x*v2.x; q2.y+=rrn*v2.y*v2.y; q2.z+=rrn*v2.z*v2.z; q2.w+=rrn*v2.w*v2.w;
                q3.x+=rrn*v3.x*v3.x; q3.y+=rrn*v3.y*v3.y; q3.z+=rrn*v3.z*v3.z; q3.w+=rrn*v3.w*v3.w;
            }
        }
        rs = wredsum(rs);
        s0 = wred4(s0); s1 = wred4(s1); s2 = wred4(s2); s3 = wred4(s3);
        q0 = wred4(q0); q1 = wred4(q1); q2 = wred4(q2); q3 = wred4(q3);

        const float inv_rs = 1.f / rs;
        float mean[16], i2v[16];
        float m4[16], qq[16];
        m4[0]=s0.x; m4[1]=s0.y; m4[2]=s0.z; m4[3]=s0.w;
        m4[4]=s1.x; m4[5]=s1.y; m4[6]=s1.z; m4[7]=s1.w;
        m4[8]=s2.x; m4[9]=s2.y; m4[10]=s2.z; m4[11]=s2.w;
        m4[12]=s3.x; m4[13]=s3.y; m4[14]=s3.z; m4[15]=s3.w;
        qq[0]=q0.x; qq[1]=q0.y; qq[2]=q0.z; qq[3]=q0.w;
        qq[4]=q1.x; qq[5]=q1.y; qq[6]=q1.z; qq[7]=q1.w;
        qq[8]=q2.x; qq[9]=q2.y; qq[10]=q2.z; qq[11]=q2.w;
        qq[12]=q3.x; qq[13]=q3.y; qq[14]=q3.z; qq[15]=q3.w;

        float logstd_sum = 0.f;
#pragma unroll
        for (int e = 0; e < 16; e++) {
            mean[e] = m4[e] * inv_rs;
            float var = fmaxf(qq[e] * inv_rs - mean[e] * mean[e], 1e-30f);
            logstd_sum += __logf(sqrtf(var) + EPSF);
            i2v[e] = 0.5f / var;
        }
        float cost_sum = 16.f * beta_v[c] + rs * logstd_sum;
        float act = 1.f / (1.f + __expf(-lambd * (beta_a[c] - cost_sum)));

        if (mode == 2) {
            if (lane == 0) {
                out[p * COUT + c] = act;
                float* op = out + 28800 + (size_t)p * 512 + c * 16;
#pragma unroll
                for (int e = 0; e < 16; e++) op[e] = mean[e];
            }
        } else {
            float zb = __logf(act + EPSF) - logstd_sum;
#pragma unroll 1
            for (int k = 0; k < 5; k++) {
                int n = lane + (k << 5);
                if (n < NCH) {
                    int sw = (n >> 1) & 3;
                    const float4* vp = reinterpret_cast<const float4*>(myV + n * 16);
                    float4 u0 = vp[0 ^ sw], u1 = vp[1 ^ sw], u2 = vp[2 ^ sw], u3 = vp[3 ^ sw];
                    float pe = 0.f;
                    float d;
                    d=u0.x-mean[0];  pe+=d*d*i2v[0];
                    d=u0.y-mean[1];  pe+=d*d*i2v[1];
                    d=u0.z-mean[2];  pe+=d*d*i2v[2];
                    d=u0.w-mean[3];  pe+=d*d*i2v[3];
                    d=u1.x-mean[4];  pe+=d*d*i2v[4];
                    d=u1.y-mean[5];  pe+=d*d*i2v[5];
                    d=u1.z-mean[6];  pe+=d*d*i2v[6];
                    d=u1.w-mean[7];  pe+=d*d*i2v[7];
                    d=u2.x-mean[8];  pe+=d*d*i2v[8];
                    d=u2.y-mean[9];  pe+=d*d*i2v[9];
                    d=u2.z-mean[10]; pe+=d*d*i2v[10];
                    d=u2.w-mean[11]; pe+=d*d*i2v[11];
                    d=u3.x-mean[12]; pe+=d*d*i2v[12];
                    d=u3.y-mean[13]; pe+=d*d*i2v[13];
                    d=u3.z-mean[14]; pe+=d*d*i2v[14];
                    d=u3.w-mean[15]; pe+=d*d*i2v[15];
                    sRZ[n * 33 + c] = zb - pe;
                }
            }
        }
    }

    if (mode != 2) {
        __syncthreads();
        float* zzp = g_zz + (size_t)p * (NCH * COUT);
        for (int idx = t; idx < NCH * COUT; idx += 256)
            zzp[idx] = sRZ[(idx >> 5) * 33 + (idx & 31)];
    }
}

// Softmax over parent axis p for every (n,c). One block per n, 1024 threads.
__global__ void __launch_bounds__(1024) softmax_kernel()
{
    __shared__ float red[32 * 33];
    __shared__ float gM[32], gS[32];
    const int n = blockIdx.x;
    const int t = threadIdx.x;
    const int c = t & 31, w = t >> 5;
    const size_t base = (size_t)n * 32 + c;

    float m = -1e30f;
    for (int p = w; p < P_TOT; p += 32)
        m = fmaxf(m, g_zz[(size_t)p * 4608 + base]);
    red[w * 33 + c] = m;
    __syncthreads();
    if (t < 32) {
        float M = red[t];
#pragma unroll
        for (int i = 1; i < 32; i++) M = fmaxf(M, red[i * 33 + t]);
        gM[t] = M;
    }
    __syncthreads();
    const float M = gM[c];

    float s = 0.f;
    for (int p = w; p < P_TOT; p += 32)
        s += __expf(g_zz[(size_t)p * 4608 + base] - M);
    red[w * 33 + c] = s;
    __syncthreads();
    if (t < 32) {
        float S = 0.f;
#pragma unroll
        for (int i = 0; i < 32; i++) S += red[i * 33 + t];
        gS[t] = 1.f / S;
    }
    __syncthreads();
    const float Sinv = gS[c];

    for (int p = w; p < P_TOT; p += 32) {
        size_t idx = (size_t)p * 4608 + base;
        g_rr[idx] = __expf(g_zz[idx] - M) * Sinv;
    }
}

extern "C" void kernel_launch(void* const* d_in, const int* in_sizes, int n_in,
                              void* d_out, int out_size)
{
    const float* pose = (const float*)d_in[1];
    const float* W    = (const float*)d_in[2];
    const float* ba   = (const float*)d_in[3];
    const float* bv   = (const float*)d_in[4];
    float* out = (float*)d_out;

    const size_t shmem = (2880 + 4752 + 8 * NCH * 16) * sizeof(float); // 104256 B
    cudaFuncSetAttribute(me_kernel, cudaFuncAttributeMaxDynamicSharedMemorySize,
                         (int)shmem);

    wtrans_kernel<<<72, 256>>>(W);
    me_kernel<<<P_TOT, 256, shmem>>>(pose, ba, bv, out, 0, 0.0f);
    softmax_kernel<<<NCH, 1024>>>();
    me_kernel<<<P_TOT, 256, shmem>>>(pose, ba, bv, out, 1, 0.0005f);
    softmax_kernel<<<NCH, 1024>>>();
    me_kernel<<<P_TOT, 256, shmem>>>(pose, ba, bv, out, 2, 0.000975f);
}

// round 3
// speedup vs baseline: 2.4303x; 1.0431x over previous
#include <cuda_runtime.h>

#define EPSF 1e-7f
#define P_TOT 900
#define NCH 144
#define COUT 32

// Scratch (no allocations allowed)
static __device__ float g_zz[P_TOT * COUT * NCH];   // [p][c][n]
static __device__ float g_rr[P_TOT * COUT * NCH];   // [p][c][n]
static __device__ float g_Wt[COUT * 4 * NCH * 4];   // [c][k][n][j]
static __device__ float g_W2[COUT * NCH * 16];      // [c][n][j][k]

// W[(n*32+c)*16 + k*4 + j] -> two layouts
__global__ void __launch_bounds__(256) wtrans_kernel(const float* __restrict__ W) {
    int t = blockIdx.x * 256 + threadIdx.x;
    if (t < NCH * COUT * 16) {
        int j = t & 3, k = (t >> 2) & 3, c = (t >> 4) & 31, n = t >> 9;
        float v = W[t];
        g_Wt[((c * 4 + k) * NCH + n) * 4 + j] = v;
        g_W2[(c * NCH + n) * 16 + j * 4 + k] = v;
    }
}

// One CTA per parent p. 8 warps.
// Phase 1 (M): warp w, lane = (h, e): c = cc*16 + 2w + h, element e. Serial
//   accumulation over n -> no reductions. Stats stashed in smem.
// Phase 2 (E): warp w handles c = {w, w+8, w+16, w+24}, lanes over n,
//   votes recomputed, zz written coalesced to gmem [p][c][n].
__global__ void __launch_bounds__(256, 4) me_kernel(
    const float* __restrict__ pose,
    const float* __restrict__ beta_a, const float* __restrict__ beta_v,
    float* __restrict__ out, int mode, float lambd)
{
    __shared__ float sA[NCH * 20];       // child poses, rows of 20 floats
    __shared__ float sRR[COUT * NCH];    // rr staged [c][n]
    __shared__ float sMean[COUT * 16];
    __shared__ float sI2v[COUT * 16];
    __shared__ float sZb[COUT];

    const int p = blockIdx.x;
    const int t = threadIdx.x;
    const int lane = t & 31, w = t >> 5;
    const int pr = p / 30, pcl = p % 30;

    // gather child poses (float4)
    for (int idx = t; idx < NCH * 4; idx += 256) {
        int n = idx >> 2, vq = idx & 3;
        int k = n >> 4, ci = n & 15;
        int q = (pr + k / 3) * 32 + pcl + (k % 3);
        float4 val = reinterpret_cast<const float4*>(pose + q * 256 + ci * 16)[vq];
        *reinterpret_cast<float4*>(sA + n * 20 + vq * 4) = val;
    }
    if (mode > 0) {
        const float* rrp = g_rr + (size_t)p * (COUT * NCH);
        for (int idx = t; idx < COUT * NCH; idx += 256) sRR[idx] = rrp[idx];
    }
    __syncthreads();

    const int h = lane >> 4, e = lane & 15;
    const int i4 = (e >> 2) << 2, j = e & 3;

#pragma unroll 1
    for (int cc = 0; cc < 2; cc++) {
        const int c = cc * 16 + (w << 1) + h;
        const float4* W2p = reinterpret_cast<const float4*>(g_W2) + c * (NCH * 4) + j;
        const float* rrow = sRR + c * NCH;
        float rs = 0.f, sv = 0.f, sq = 0.f;
#pragma unroll 4
        for (int n = 0; n < NCH; n++) {
            float rrn = (mode == 0) ? 0.03125f : rrow[n];
            float4 wv = W2p[n << 2];
            float4 av = *reinterpret_cast<const float4*>(sA + n * 20 + i4);
            float v = av.x * wv.x + av.y * wv.y + av.z * wv.z + av.w * wv.w;
            rs += rrn;
            sv += rrn * v;
            sq += rrn * v * v;
        }
        const float inv = 1.f / rs;
        const float mean = sv * inv;
        const float var = fmaxf(sq * inv - mean * mean, 1e-30f);
        float l = __logf(sqrtf(var) + EPSF);
        l += __shfl_xor_sync(0xffffffffu, l, 1);
        l += __shfl_xor_sync(0xffffffffu, l, 2);
        l += __shfl_xor_sync(0xffffffffu, l, 4);
        l += __shfl_xor_sync(0xffffffffu, l, 8);
        const float cost = 16.f * beta_v[c] + rs * l;
        const float act = 1.f / (1.f + __expf(-lambd * (beta_a[c] - cost)));

        if (mode == 2) {
            out[28800 + (size_t)p * 512 + c * 16 + e] = mean;
            if (e == 0) out[p * COUT + c] = act;
        } else {
            sMean[c * 16 + e] = mean;
            sI2v[c * 16 + e] = 0.5f / var;
            if (e == 0) sZb[c] = __logf(act + EPSF) - l;
        }
    }
    if (mode == 2) return;
    __syncthreads();

    float* zzp = g_zz + (size_t)p * (COUT * NCH);
#pragma unroll 1
    for (int ce = 0; ce < 4; ce++) {
        const int c = w + ce * 8;
        const float4* Wp = reinterpret_cast<const float4*>(g_Wt) + c * (4 * NCH);
        const float4* Mp = reinterpret_cast<const float4*>(sMean + c * 16);
        const float4* Yp = reinterpret_cast<const float4*>(sI2v + c * 16);
        const float zb = sZb[c];
#pragma unroll 1
        for (int k = 0; k < 5; k++) {
            int n = lane + (k << 5);
            if (n < NCH) {
                const float4* Ap = reinterpret_cast<const float4*>(sA + n * 20);
                float4 b0 = Wp[n], b1 = Wp[NCH + n], b2 = Wp[2 * NCH + n], b3 = Wp[3 * NCH + n];
                float pe = 0.f;
#pragma unroll
                for (int r = 0; r < 4; r++) {
                    float4 a = Ap[r];
                    float4 m = Mp[r];
                    float4 y = Yp[r];
                    float v, d;
                    v = a.x*b0.x + a.y*b1.x + a.z*b2.x + a.w*b3.x; d = v - m.x; pe += d*d*y.x;
                    v = a.x*b0.y + a.y*b1.y + a.z*b2.y + a.w*b3.y; d = v - m.y; pe += d*d*y.y;
                    v = a.x*b0.z + a.y*b1.z + a.z*b2.z + a.w*b3.z; d = v - m.z; pe += d*d*y.z;
                    v = a.x*b0.w + a.y*b1.w + a.z*b2.w + a.w*b3.w; d = v - m.w; pe += d*d*y.w;
                }
                zzp[c * NCH + n] = zb - pe;
            }
        }
    }
}

// Softmax over parent axis p for every (n,c) on layout [p][c][n].
// grid (32 c, 9 n-chunks), 512 threads: 32 p-stripes x 16 n.
__global__ void __launch_bounds__(512) softmax_kernel()
{
    __shared__ float red[512];
    __shared__ float gv[16];
    const int c = blockIdx.x, nb = blockIdx.y;
    const int t = threadIdx.x, nl = t & 15, st = t >> 4;
    const int base = c * NCH + nb * 16 + nl;

    float m = -1e30f;
    for (int p = st; p < P_TOT; p += 32)
        m = fmaxf(m, g_zz[(size_t)p * 4608 + base]);
    red[t] = m;
    __syncthreads();
    if (t < 16) {
        float M = red[t];
#pragma unroll
        for (int i = 1; i < 32; i++) M = fmaxf(M, red[i * 16 + t]);
        gv[t] = M;
    }
    __syncthreads();
    const float M = gv[nl];

    float s = 0.f;
    for (int p = st; p < P_TOT; p += 32)
        s += __expf(g_zz[(size_t)p * 4608 + base] - M);
    red[t] = s;
    __syncthreads();
    if (t < 16) {
        float S = 0.f;
#pragma unroll
        for (int i = 0; i < 32; i++) S += red[i * 16 + t];
        gv[t] = 1.f / S;
    }
    __syncthreads();
    const float Sinv = gv[nl];

    for (int p = st; p < P_TOT; p += 32) {
        size_t idx = (size_t)p * 4608 + base;
        g_rr[idx] = __expf(g_zz[idx] - M) * Sinv;
    }
}

extern "C" void kernel_launch(void* const* d_in, const int* in_sizes, int n_in,
                              void* d_out, int out_size)
{
    const float* pose = (const float*)d_in[1];
    const float* W    = (const float*)d_in[2];
    const float* ba   = (const float*)d_in[3];
    const float* bv   = (const float*)d_in[4];
    float* out = (float*)d_out;

    wtrans_kernel<<<288, 256>>>(W);
    me_kernel<<<P_TOT, 256>>>(pose, ba, bv, out, 0, 0.0f);
    softmax_kernel<<<dim3(32, 9), 512>>>();
    me_kernel<<<P_TOT, 256>>>(pose, ba, bv, out, 1, 0.0005f);
    softmax_kernel<<<dim3(32, 9), 512>>>();
    me_kernel<<<P_TOT, 256>>>(pose, ba, bv, out, 2, 0.000975f);
}